// round 5
// baseline (speedup 1.0000x reference)
#include <cuda_runtime.h>
#include <cstdint>

// Problem constants
#define TOK 8192      // b*n tokens
#define D   1024
#define H   8
#define E   16
#define CS  2048
#define COLS (H*E)    // 128 projection columns

// -------- device scratch (static; no allocations allowed) --------
__device__ float g_S[COLS];                          // column sums of W
__device__ __align__(16) float g_W[D * COLS];        // W' = W - S/D, [d][col]   (512 KB)
__device__ __align__(16) float g_cbn[H * CS * E];    // L2-normalized codebook   (1 MB)
__device__ __align__(16) float g_P[TOK * COLS];      // projections [t][h*16+e]  (4 MB)

// -------- 1: column sums S[h,e] = sum_d W[h,d,e] --------
__global__ void prepS_kernel(const float* __restrict__ W) {
    int col = blockIdx.x;            // h*16+e, 128 blocks
    int h = col >> 4, e = col & 15;
    float s = 0.f;
    for (int d = threadIdx.x; d < D; d += 256)
        s += W[(h * D + d) * E + e];
    __shared__ float red[256];
    red[threadIdx.x] = s;
    __syncthreads();
    for (int off = 128; off > 0; off >>= 1) {
        if (threadIdx.x < off) red[threadIdx.x] += red[threadIdx.x + off];
        __syncthreads();
    }
    if (threadIdx.x == 0) g_S[col] = red[0];
}

// -------- 2: W'[d][col] = W[h,d,e] - S[col]/D --------
__global__ void prepW_kernel(const float* __restrict__ W) {
    int i = blockIdx.x * 256 + threadIdx.x;   // 131072 = D*COLS
    int d = i >> 7, col = i & 127;
    int h = col >> 4, e = col & 15;
    g_W[i] = W[(h * D + d) * E + e] - g_S[col] * (1.0f / 1024.0f);
}

// -------- 3: normalized codebook (row-major, one thread per code) --------
__global__ void prepCB_kernel(const float* __restrict__ CB) {
    int i = blockIdx.x * 256 + threadIdx.x;   // 16384 codes = H*CS
    const float4* src = (const float4*)(CB + (size_t)i * E);
    float4 v[4];
    float s = 0.f;
#pragma unroll
    for (int k = 0; k < 4; ++k) {
        v[k] = src[k];
        s += v[k].x * v[k].x + v[k].y * v[k].y + v[k].z * v[k].z + v[k].w * v[k].w;
    }
    float r = 1.0f / sqrtf(s + 1e-12f);
    float4* dst = (float4*)(g_cbn + (size_t)i * E);
#pragma unroll
    for (int k = 0; k < 4; ++k)
        dst[k] = make_float4(v[k].x * r, v[k].y * r, v[k].z * r, v[k].w * r);
}

// -------- 4: projection GEMM  P[t][col] = x[t,:] @ W' --------
__global__ __launch_bounds__(256) void proj_kernel(const float* __restrict__ x) {
    __shared__ float xs[64][33];     // [dd][token], padded
    int t0 = blockIdx.x * 32;
    int tid = threadIdx.x;
    int tg = tid & 7;                // tokens tg, tg+8, tg+16, tg+24
    int cq = tid >> 3;               // 0..31 -> cols 4cq..4cq+3
    float acc[4][4];
#pragma unroll
    for (int i = 0; i < 4; ++i)
#pragma unroll
        for (int k = 0; k < 4; ++k) acc[i][k] = 0.f;

    for (int ch = 0; ch < 16; ++ch) {
        int base = ch * 64;
#pragma unroll
        for (int j = 0; j < 8; ++j) {
            int i = j * 256 + tid;            // 0..2047 over the 32x64 tile
            int t = i >> 6, dd = i & 63;
            xs[dd][t] = x[(size_t)(t0 + t) * D + base + dd];
        }
        __syncthreads();
#pragma unroll 4
        for (int dd = 0; dd < 64; ++dd) {
            float4 w = *(const float4*)&g_W[(size_t)(base + dd) * COLS + 4 * cq];
#pragma unroll
            for (int i = 0; i < 4; ++i) {
                float xv = xs[dd][tg + 8 * i];
                acc[i][0] += xv * w.x;
                acc[i][1] += xv * w.y;
                acc[i][2] += xv * w.z;
                acc[i][3] += xv * w.w;
            }
        }
        __syncthreads();
    }
#pragma unroll
    for (int i = 0; i < 4; ++i)
        *(float4*)&g_P[(size_t)(t0 + tg + 8 * i) * COLS + 4 * cq] =
            make_float4(acc[i][0], acc[i][1], acc[i][2], acc[i][3]);
}

// -------- 5: similarity scan + in-warp argmax (FLOAT32 index output) --------
__global__ __launch_bounds__(256) void sim_kernel(float* __restrict__ out) {
    int bid = blockIdx.x;            // 2048 blocks
    int h = bid & 7;
    int tq = bid >> 3;               // 0..255
    int wid = threadIdx.x >> 5;
    int lane = threadIdx.x & 31;
    int tbase = tq * 32 + wid * 4;   // 4 tokens per warp

    float q[4][16];
#pragma unroll
    for (int tt = 0; tt < 4; ++tt) {
        const float4* qp = (const float4*)&g_P[(size_t)(tbase + tt) * COLS + h * E];
#pragma unroll
        for (int k = 0; k < 4; ++k) {
            float4 v = qp[k];
            q[tt][4 * k + 0] = v.x;
            q[tt][4 * k + 1] = v.y;
            q[tt][4 * k + 2] = v.z;
            q[tt][4 * k + 3] = v.w;
        }
    }

    const float4* cb = (const float4*)&g_cbn[(size_t)h * CS * E];
    float best[4];
    int idx[4];
#pragma unroll
    for (int tt = 0; tt < 4; ++tt) { best[tt] = -3.402823466e38f; idx[tt] = 0; }

    for (int j = 0; j < 64; ++j) {
        int c = j * 32 + lane;                 // this lane's code
        float4 c0 = cb[c * 4 + 0];
        float4 c1 = cb[c * 4 + 1];
        float4 c2 = cb[c * 4 + 2];
        float4 c3 = cb[c * 4 + 3];
        float cv[16] = { c0.x, c0.y, c0.z, c0.w,
                         c1.x, c1.y, c1.z, c1.w,
                         c2.x, c2.y, c2.z, c2.w,
                         c3.x, c3.y, c3.z, c3.w };
#pragma unroll
        for (int tt = 0; tt < 4; ++tt) {
            float s0 = 0.f, s1 = 0.f;
#pragma unroll
            for (int e = 0; e < 8; ++e) {
                s0 += q[tt][e] * cv[e];
                s1 += q[tt][8 + e] * cv[8 + e];
            }
            float s = s0 + s1;
            if (s > best[tt]) { best[tt] = s; idx[tt] = c; }  // strict > keeps first max
        }
    }

    // warp argmax reduce (tie -> smaller index, matching argmax-first semantics)
#pragma unroll
    for (int tt = 0; tt < 4; ++tt) {
        float b = best[tt];
        int ix = idx[tt];
#pragma unroll
        for (int off = 16; off > 0; off >>= 1) {
            float ob = __shfl_xor_sync(0xffffffffu, b, off);
            int oi = __shfl_xor_sync(0xffffffffu, ix, off);
            if (ob > b || (ob == b && oi < ix)) { b = ob; ix = oi; }
        }
        if (lane == 0)
            out[(size_t)(tbase + tt) * H + h] = (float)ix;   // indices as float32
    }
}

extern "C" void kernel_launch(void* const* d_in, const int* in_sizes, int n_in,
                              void* d_out, int out_size) {
    const float* x = nullptr;
    const float* W = nullptr;
    const float* CB = nullptr;
    // Match by element count OR byte count (both sets are mutually distinct).
    for (int i = 0; i < n_in; ++i) {
        long s = (long)in_sizes[i];
        if (s == 8388608L || s == 33554432L)      x  = (const float*)d_in[i];
        else if (s == 131072L || s == 524288L)    W  = (const float*)d_in[i];
        else if (s == 262144L || s == 1048576L)   CB = (const float*)d_in[i];
    }
    // Positional fallback: metadata order is (x, rand_projs, codebook).
    if (!x || !W || !CB) {
        if (n_in >= 3) {
            x  = (const float*)d_in[0];
            W  = (const float*)d_in[1];
            CB = (const float*)d_in[2];
        }
    }
    prepS_kernel<<<128, 256>>>(W);
    prepW_kernel<<<512, 256>>>(W);
    prepCB_kernel<<<64, 256>>>(CB);
    proj_kernel<<<256, 256>>>(x);
    sim_kernel<<<2048, 256>>>((float*)d_out);
}